// round 5
// baseline (speedup 1.0000x reference)
#include <cuda_runtime.h>
#include <cstdint>
#include <cstddef>

#define WIDTH  2048
#define DEPTH  8
#define DP1    9
#define TMOD   242          // 30*DEPTH + 2
#define WD     16384        // WIDTH*DEPTH
#define NSPLIT 32           // i-splits (blockIdx.y), 64 i each
#define KBLK   16           // k-blocks  (blockIdx.x), 1024 k each
#define CHUNK  64           // WIDTH / NSPLIT

// d_out layout (float32, reference return order)
#define OFF_OUT   0ULL
#define OFF_STATE 1ULL
#define OFF_SA    18433ULL
#define OFF_SG    4478977ULL
#define OFF_OG    4495361ULL
#define OFF_GRAD  8955905ULL
#define OFF_OWG   42510337ULL

#define N_SAOG    (WIDTH * DP1 * TMOD)     // 4460544
#define NQ_SAOG   1115135                  // quads idx = 3+4q
#define NQ_GROW   4095                     // per-row quads k = 3+4q

// scratch (allocation-free)
__device__ float g_hpart[NSPLIT][WD];     // hidden partials (2 MB)
__device__ float g_cpart[KBLK][WD];       // contrib partials (1 MB)
__device__ float g_m[WD];
__device__ float g_mshift[WD];            // g_mshift[t] = m[t+3]
__device__ float g_aprev[WD];
__device__ float g_out_acc;

__device__ __forceinline__ int posmod(int v, int m) {
    int r = v % m;
    return r < 0 ? r + m : r;
}

// ---------------------------------------------------------------------------
// K1: single pass over W, both reductions, float4 loads.
// Thread owns 4 consecutive k (same j = k>>3; d in {0-3} (even lane) or
// {4-7} (odd lane)). Warp covers 128 k = 16 j.
//   hidden[k]    = sum_i W[i*WD+k] * state[i, k&7]
//   contrib[i,d] = sum_j W[i*WD+j*8+d] * sg[j*8+d]   (d=0 slot zeroed)
// ---------------------------------------------------------------------------
__global__ void k_fusedW(const float* __restrict__ W,
                         const float* __restrict__ state_in,
                         const float* __restrict__ sgrad) {
    __shared__ float ss[CHUNK * 8];          // 2 KB state chunk
    __shared__ float csm[8 * CHUNK * 8];     // 16 KB per-warp contrib partials

    const int tid = threadIdx.x;
    const int k4  = blockIdx.x * 1024 + tid * 4;
    const int i0  = blockIdx.y * CHUNK;
    const int wid = tid >> 5, lane = tid & 31;
    const int dbase = (tid & 1) * 4;

    if (blockIdx.x == 0 && blockIdx.y == 0 && tid == 0) g_out_acc = 0.f;

    float4 sgf4 = *reinterpret_cast<const float4*>(sgrad + k4);
    if (dbase == 0) sgf4.x = 0.f;            // d==0 contributes nothing

    for (int idx = tid; idx < CHUNK * 8; idx += 256) {
        int i = idx >> 3, dd = idx & 7;
        ss[idx] = state_in[(size_t)(i0 + i) * DP1 + dd];
    }
    __syncthreads();

    const float* Wp = W + (size_t)i0 * WD + k4;
    float4 hacc = make_float4(0.f, 0.f, 0.f, 0.f);

#pragma unroll 8
    for (int i = 0; i < CHUNK; ++i) {
        float4 w4 = *reinterpret_cast<const float4*>(Wp + (size_t)i * WD);
        float4 sv = *reinterpret_cast<const float4*>(&ss[i * 8 + dbase]);
        hacc.x = fmaf(w4.x, sv.x, hacc.x);
        hacc.y = fmaf(w4.y, sv.y, hacc.y);
        hacc.z = fmaf(w4.z, sv.z, hacc.z);
        hacc.w = fmaf(w4.w, sv.w, hacc.w);

        float4 p;
        p.x = w4.x * sgf4.x;
        p.y = w4.y * sgf4.y;
        p.z = w4.z * sgf4.z;
        p.w = w4.w * sgf4.w;
        // parity-preserving reduction over the warp's 16 j
#pragma unroll
        for (int dist = 2; dist <= 16; dist <<= 1) {
            p.x += __shfl_xor_sync(0xffffffffu, p.x, dist);
            p.y += __shfl_xor_sync(0xffffffffu, p.y, dist);
            p.z += __shfl_xor_sync(0xffffffffu, p.z, dist);
            p.w += __shfl_xor_sync(0xffffffffu, p.w, dist);
        }
        if (lane < 2)
            *reinterpret_cast<float4*>(&csm[(wid * CHUNK + i) * 8 + lane * 4]) = p;
    }
    *reinterpret_cast<float4*>(&g_hpart[blockIdx.y][k4]) = hacc;

    __syncthreads();
    for (int idx = tid; idx < CHUNK * 8; idx += 256) {
        float s = 0.f;
#pragma unroll
        for (int w = 0; w < 8; ++w) s += csm[w * CHUNK * 8 + idx];
        g_cpart[blockIdx.x][(size_t)i0 * 8 + idx] = s;
    }
}

// ---------------------------------------------------------------------------
// K2: finalize — state/owg, contrib sum, output dot, full sg logic, m-shift.
// tia(a) = time + 2a - 14 (mod 242); tia==time only at a=7, (tia±1)!=time
// for all a -> all sa/og reads at a<7 hit the ORIGINAL arrays; at a=7 the
// only aliased read is this thread's own fresh state value.
// ---------------------------------------------------------------------------
__global__ void k_finalize(float* __restrict__ out,
                           const float* __restrict__ x,
                           const float* __restrict__ ow,
                           const float* __restrict__ sa_in,
                           const float* __restrict__ og_in,
                           const int* __restrict__ time_p) {
    const int k = blockIdx.x * blockDim.x + threadIdx.x;   // 0..WD-1
    const int w = k >> 3, a = k & 7;

    float h = 0.f;
#pragma unroll
    for (int c = 0; c < NSPLIT; ++c) h += g_hpart[c][k];
    float s = fmaxf(h, 0.f);

    float cb = 0.f;
#pragma unroll
    for (int b = 0; b < KBLK; ++b) cb += g_cpart[b][k];
    float cbn = __shfl_down_sync(0xffffffffu, cb, 1);   // slot d = a+1

    size_t o = (size_t)w * DP1 + a + 1;
    out[OFF_STATE + o] = s;
    out[OFF_OWG + o]   = s;
    float v = ow[o] * s;
    if (a == 0) {
        float xv = x[w];
        out[OFF_STATE + (size_t)w * DP1] = xv;
        out[OFF_OWG   + (size_t)w * DP1] = xv;
        v = fmaf(ow[(size_t)w * DP1], xv, v);
    }

    const int time = *time_p;
    const int tia = posmod(time - 2 * DEPTH + 2 * (a + 1), TMOD);
    float sgv, rg, aprev;
    if (a < DEPTH - 1) {
        int t1 = (tia + 1) % TMOD;
        float rmv = sa_in[((size_t)w * DP1 + a + 2) * TMOD + t1];
        sgv = fmaf(rmv > 0.f ? 1.f : 0.f, cbn,
                   og_in[((size_t)w * DP1 + a + 1) * TMOD + tia]);
        rg = (sa_in[((size_t)w * DP1 + a + 1) * TMOD + tia] > 0.f) ? 1.f : 0.f;
        aprev = sa_in[((size_t)w * DP1 + a) * TMOD + posmod(tia - 1, TMOD)];
    } else {
        sgv = ow[(size_t)w * DP1 + DEPTH];
        rg = (s > 0.f) ? 1.f : 0.f;
        aprev = sa_in[((size_t)w * DP1 + DEPTH - 1) * TMOD + posmod(time - 1, TMOD)];
    }
    out[OFF_SG + k] = sgv;
    float mval = sgv * rg;
    g_m[k] = mval;
    if (k >= 3) g_mshift[k - 3] = mval;
    g_aprev[k] = aprev;

    __shared__ float red[8];
#pragma unroll
    for (int off = 16; off; off >>= 1)
        v += __shfl_down_sync(0xffffffffu, v, off);
    if ((threadIdx.x & 31) == 0) red[threadIdx.x >> 5] = v;
    __syncthreads();
    if (threadIdx.x == 0) {
        float t = 0.f;
#pragma unroll
        for (int i = 0; i < 8; ++i) t += red[i];
        atomicAdd(&g_out_acc, t);
    }
}

// ---------------------------------------------------------------------------
// K3: sa / og copies, SECTOR-ALIGNED stores (quad idx = 3+4q).
// ---------------------------------------------------------------------------
__global__ void k_saog(float* __restrict__ out,
                       const float* __restrict__ sa_in,
                       const float* __restrict__ og_in,
                       const float* __restrict__ ow,
                       const int* __restrict__ time_p) {
    const int time = *time_p;
    const int q = blockIdx.x * blockDim.x + threadIdx.x;
    if (q >= NQ_SAOG) return;
    const int idx = 3 + 4 * q;

    const float4* sa4 = reinterpret_cast<const float4*>(sa_in);
    const float4* og4 = reinterpret_cast<const float4*>(og_in);
    float4 sA = sa4[q], sB = sa4[q + 1];
    float4 oA = og4[q], oB = og4[q + 1];
    float sv[4] = {sA.w, sB.x, sB.y, sB.z};
    float ov[4] = {oA.w, oB.x, oB.y, oB.z};

    int t  = idx % TMOD;
    int wc = idx / TMOD;
#pragma unroll
    for (int e = 0; e < 4; ++e) {
        int tt = t + e, wcc = wc;
        if (tt >= TMOD) { tt -= TMOD; ++wcc; }
        if (tt == time) {
            sv[e] = out[OFF_STATE + wcc];
            ov[e] = ow[wcc];
        }
    }
    *reinterpret_cast<float4*>(&out[OFF_SA + idx]) = make_float4(sv[0], sv[1], sv[2], sv[3]);
    *reinterpret_cast<float4*>(&out[OFF_OG + idx]) = make_float4(ov[0], ov[1], ov[2], ov[3]);

    if (q == 0) {
#pragma unroll
        for (int e = 0; e < 3; ++e) {
            out[OFF_SA + e] = (e == time) ? out[OFF_STATE] : sa_in[e];
            out[OFF_OG + e] = (e == time) ? ow[0] : og_in[e];
        }
    }
    if (q == NQ_SAOG - 1) {
        const int it = N_SAOG - 1;
        int tt = it % TMOD, wcc = it / TMOD;
        out[OFF_SA + it] = (tt == time) ? out[OFF_STATE + wcc] : sa_in[it];
        out[OFF_OG + it] = (tt == time) ? ow[wcc] : og_in[it];
    }
}

// ---------------------------------------------------------------------------
// K4: gradients[i,j,a] = act_prev[i,a] * m[j,a]; one aligned load + one
// aligned store per quad via the pre-shifted m array.
// ---------------------------------------------------------------------------
__global__ void k_grad(float* __restrict__ out) {
    const int i = blockIdx.x;
    const int tid = threadIdx.x;
    if (i == 0 && tid == 0) out[OFF_OUT] = g_out_acc;

    const float* ap = g_aprev + (size_t)i * 8;
    float4 apv;
    if ((tid & 1) == 0)
        apv = make_float4(__ldg(ap + 3), __ldg(ap + 4), __ldg(ap + 5), __ldg(ap + 6));
    else
        apv = make_float4(__ldg(ap + 7), __ldg(ap + 0), __ldg(ap + 1), __ldg(ap + 2));

    float* dst = out + OFF_GRAD + (size_t)i * WD;
    const float4* ms4 = reinterpret_cast<const float4*>(g_mshift);

    for (int q = tid; q < NQ_GROW; q += 256) {
        float4 mv = ms4[q];   // m[4q+3 .. 4q+6]
        float4 v = make_float4(apv.x * mv.x, apv.y * mv.y, apv.z * mv.z, apv.w * mv.w);
        *reinterpret_cast<float4*>(dst + 3 + 4 * q) = v;
    }
    if (tid == 0) {
        dst[0] = __ldg(ap + 0) * g_m[0];
        dst[1] = __ldg(ap + 1) * g_m[1];
        dst[2] = __ldg(ap + 2) * g_m[2];
    } else if (tid == 1) {
        dst[WD - 1] = __ldg(ap + 7) * g_m[WD - 1];
    }
}

// ---------------------------------------------------------------------------
extern "C" void kernel_launch(void* const* d_in, const int* in_sizes, int n_in,
                              void* d_out, int out_size) {
    const float* x    = (const float*)d_in[0];
    const float* W    = (const float*)d_in[1];
    const float* ow   = (const float*)d_in[2];
    const float* st   = (const float*)d_in[3];
    const float* sa   = (const float*)d_in[4];
    const float* sgr  = (const float*)d_in[5];
    const float* og   = (const float*)d_in[6];
    const int*   tim  = (const int*)d_in[7];
    float* out = (float*)d_out;

    k_fusedW<<<dim3(KBLK, NSPLIT), 256>>>(W, st, sgr);
    k_finalize<<<WD / 256, 256>>>(out, x, ow, sa, og, tim);
    k_saog<<<(NQ_SAOG + 255) / 256, 256>>>(out, sa, og, ow, tim);
    k_grad<<<WIDTH, 256>>>(out);
}